// round 6
// baseline (speedup 1.0000x reference)
#include <cuda_runtime.h>
#include <cstdint>

// Problem constants (fixed shapes per reference setup_inputs)
#define NCLASS 19
#define HW (512 * 1024)            // 524288 (power of two -> /HW is a shift)
#define NBATCH 8
#define NPIX (NBATCH * HW)         // 4194304 pixels
#define NVEC (NPIX / 4)            // 1048576 float4 groups
#define THREADS 256
#define GRID 2048
#define ITERS 2                    // GRID*THREADS*ITERS == NVEC exactly
#define CHUNK 6                    // channels loaded per batch (1 + 3*6 = 19)

// Scratch counters in device globals (no allocation allowed).
// Zero-initialized at load; finalizing block resets them -> clean per replay.
__device__ unsigned int g_pred_cnt[NCLASS];
__device__ unsigned int g_true_cnt[NCLASS];
__device__ unsigned int g_inter_cnt[NCLASS];
__device__ unsigned int g_ticket;

__global__ __launch_bounds__(THREADS)
void iou_fused_kernel(const float* __restrict__ preds,
                      const int*   __restrict__ targets,
                      float*       __restrict__ out) {
    __shared__ unsigned int s_pred[NCLASS];
    __shared__ unsigned int s_true[NCLASS];
    __shared__ unsigned int s_inter[NCLASS];
    __shared__ bool s_is_last;

    const int t = threadIdx.x;
    if (t < NCLASS) {
        s_pred[t]  = 0u;
        s_true[t]  = 0u;
        s_inter[t] = 0u;
    }
    __syncthreads();

    const size_t ch_stride4 = HW / 4;   // float4 stride between channels

#pragma unroll
    for (int it = 0; it < ITERS; ++it) {
        // Consecutive blocks stream consecutive 16KB tiles each iteration.
        const unsigned int vidx = ((unsigned)it * GRID + blockIdx.x) * THREADS + t;
        const unsigned int i = vidx * 4;               // pixel index
        const unsigned int b = i / HW;                 // batch (shift)
        // preds elem offset for (b, c, s): i + b*(C-1)*HW + c*HW
        const size_t base = (size_t)i + (size_t)b * (size_t)(NCLASS - 1) * HW;
        const float4* p4 = reinterpret_cast<const float4*>(preds + base);

        // Argmax over channels, 4 pixels per thread.
        // Channels batched in groups of CHUNK so 6 LDG.128 are in flight
        // before any compare consumes them (MLP ~ 6 per thread).
        float4 best = __ldcs(p4);
        int bx = 0, by = 0, bz = 0, bw = 0;

#pragma unroll
        for (int cb = 1; cb < NCLASS; cb += CHUNK) {
            float4 v[CHUNK];
#pragma unroll
            for (int j = 0; j < CHUNK; ++j)
                v[j] = __ldcs(p4 + (size_t)(cb + j) * ch_stride4);
#pragma unroll
            for (int j = 0; j < CHUNK; ++j) {
                const int c = cb + j;   // strict > keeps first max (JAX argmax)
                // Flat select form -> FSETP + SEL/FSEL, no branches in the body.
                bool gx = v[j].x > best.x;
                bool gy = v[j].y > best.y;
                bool gz = v[j].z > best.z;
                bool gw = v[j].w > best.w;
                best.x = gx ? v[j].x : best.x;  bx = gx ? c : bx;
                best.y = gy ? v[j].y : best.y;  by = gy ? c : by;
                best.z = gz ? v[j].z : best.z;  bz = gz ? c : bz;
                best.w = gw ? v[j].w : best.w;  bw = gw ? c : bw;
            }
        }

        const int4 tg = __ldcs(reinterpret_cast<const int4*>(targets) + vidx);

        atomicAdd(&s_pred[bx], 1u);
        atomicAdd(&s_pred[by], 1u);
        atomicAdd(&s_pred[bz], 1u);
        atomicAdd(&s_pred[bw], 1u);

        atomicAdd(&s_true[tg.x], 1u);
        atomicAdd(&s_true[tg.y], 1u);
        atomicAdd(&s_true[tg.z], 1u);
        atomicAdd(&s_true[tg.w], 1u);

        if (bx == tg.x) atomicAdd(&s_inter[bx], 1u);
        if (by == tg.y) atomicAdd(&s_inter[by], 1u);
        if (bz == tg.z) atomicAdd(&s_inter[bz], 1u);
        if (bw == tg.w) atomicAdd(&s_inter[bw], 1u);
    }

    __syncthreads();

    // ---- global accumulate + fence ----
    if (t < NCLASS) {
        if (s_pred[t])  atomicAdd(&g_pred_cnt[t],  s_pred[t]);
        if (s_true[t])  atomicAdd(&g_true_cnt[t],  s_true[t]);
        if (s_inter[t]) atomicAdd(&g_inter_cnt[t], s_inter[t]);
        __threadfence();
    }
    __syncthreads();

    // ---- ticket: last block finalizes ----
    if (t == 0) {
        unsigned int old = atomicAdd(&g_ticket, 1u);
        s_is_last = (old == (unsigned int)(gridDim.x - 1));
    }
    __syncthreads();

    if (s_is_last) {
        __shared__ float iou[NCLASS];
        if (t < NCLASS) {
            unsigned int inter = *(volatile unsigned int*)&g_inter_cnt[t];
            unsigned int pc    = *(volatile unsigned int*)&g_pred_cnt[t];
            unsigned int tc    = *(volatile unsigned int*)&g_true_cnt[t];
            unsigned int uni = pc + tc - inter;
            float v = (tc > 0u) ? ((float)inter / (float)max(uni, 1u)) : 0.0f;
            iou[t] = v;
            if (t >= 1) out[t - 1] = v;
            g_pred_cnt[t]  = 0u;
            g_true_cnt[t]  = 0u;
            g_inter_cnt[t] = 0u;
        }
        __syncthreads();
        if (t == 0) {
            float s = 0.0f;
#pragma unroll
            for (int c = 1; c < NCLASS; ++c) s += iou[c];
            out[NCLASS - 1] = s / (float)(NCLASS - 1);
            g_ticket = 0u;
        }
    }
}

extern "C" void kernel_launch(void* const* d_in, const int* in_sizes, int n_in,
                              void* d_out, int out_size) {
    const float* preds   = (const float*)d_in[0];
    const int*   targets = (const int*)d_in[1];
    float*       out     = (float*)d_out;

    iou_fused_kernel<<<GRID, THREADS>>>(preds, targets, out);
}